// round 12
// baseline (speedup 1.0000x reference)
#include <cuda_runtime.h>
#include <cuda_fp16.h>
#include <math.h>

#define BATCH 16
#define HH 1024
#define WW 1024
#define NPIX (HH*WW)
#define NTOT (BATCH*NPIX)
#define NW   (NTOT/32)          // 524288 bitmap words
#define NODE (NW*16)            // <=16 runs per 32-bit word

// Value encoding in par[]: v = idx*2 + (flag ? 0 : 1) for root slots;
// non-root slots hold parent pointer idx in bits [1..], bit0 = don't-care (1).
// atomicMin: idx dominates; flagged < unflagged at equal idx, so flags never
// clear and links only decrease idx.

// Scratch (__device__ globals; no allocation)
__device__ int g_parP[NODE];
__device__ int g_parT[NODE];
__device__ unsigned int g_bmP[NW];
__device__ unsigned int g_bmT[NW];
__device__ __half2 g_loss[NTOT/2];  // fp16 per-pixel BCE loss (32 MB)
__device__ double g_sum;
__device__ double g_psum[64];

// ---------------------------------------------------------------------------
__global__ void k_zero() {
    int t = threadIdx.x;
    if (t == 0) g_sum = 0.0;
    if (t < 64) g_psum[t] = 0.0;
}

// ---------------------------------------------------------------------------
// k_init: bitmaps + fp16 loss + 0.5*sum(loss) + parent init with per-run
// mistake flags baked into the initial values. One block = one 1024-px row.
// ---------------------------------------------------------------------------
__global__ __launch_bounds__(256) void k_init(const float* __restrict__ preds,
                                              const float* __restrict__ targs) {
    __shared__ unsigned char snP[256], snT[256];
    __shared__ float ssum[8];
    int t = threadIdx.x;
    int i4 = blockIdx.x * 256 + t;
    float4 p  = reinterpret_cast<const float4*>(preds)[i4];
    float4 tg = reinterpret_cast<const float4*>(targs)[i4];
    unsigned int nP = (unsigned int)(p.x  > 0.5f) | ((unsigned int)(p.y  > 0.5f) << 1)
                    | ((unsigned int)(p.z  > 0.5f) << 2) | ((unsigned int)(p.w  > 0.5f) << 3);
    unsigned int nT = (unsigned int)(tg.x > 0.0f) | ((unsigned int)(tg.y > 0.0f) << 1)
                    | ((unsigned int)(tg.z > 0.0f) << 2) | ((unsigned int)(tg.w > 0.0f) << 3);
    snP[t] = (unsigned char)nP;
    snT[t] = (unsigned char)nT;

    float pv[4] = {p.x, p.y, p.z, p.w};
    float tv[4] = {tg.x, tg.y, tg.z, tg.w};
    float lv[4];
    float local = 0.0f;
#pragma unroll
    for (int j = 0; j < 4; j++) {
        float pp = pv[j];
        float l = fmaxf(pp, 0.0f) - pp * tv[j] + log1pf(expf(-fabsf(pp)));
        lv[j] = l;
        local += l;
    }
    __half2 h0 = __floats2half2_rn(lv[0], lv[1]);
    __half2 h1 = __floats2half2_rn(lv[2], lv[3]);
    uint2 packed;
    packed.x = *reinterpret_cast<unsigned int*>(&h0);
    packed.y = *reinterpret_cast<unsigned int*>(&h1);
    reinterpret_cast<uint2*>(g_loss)[i4] = packed;
    __syncthreads();

    if (t < 64) {
        int w = t >> 1;
        int half = t & 1;
        const unsigned char* sn = half ? snT : snP;
        const unsigned char* so = half ? snP : snT;
        unsigned int word = 0, other = 0;
#pragma unroll
        for (int j = 0; j < 8; j++) {
            word  |= ((unsigned int)sn[w * 8 + j]) << (4 * j);
            other |= ((unsigned int)so[w * 8 + j]) << (4 * j);
        }
        int gw = blockIdx.x * 32 + w;
        if (half) g_bmT[gw] = word;
        else      g_bmP[gw] = word;

        // per-run mistake flags
        unsigned int mistake = word & ~other;
        unsigned int rr = word & ~(word << 1);
        unsigned int fmask = 0;
        int ridx = 0;
        while (rr) {
            int s = __ffs(rr) - 1; rr &= rr - 1;
            int e = rr ? (__ffs(rr) - 1) : 32;
            unsigned int seg = (e < 32 ? ((1u << e) - 1u) : ~0u) & (~0u << s);
            if (mistake & seg) fmask |= (1u << ridx);
            ridx++;
        }
        int nb2 = gw * 32;   // (gw*16)*2
        int4* dst = (half ? reinterpret_cast<int4*>(g_parT)
                          : reinterpret_cast<int4*>(g_parP)) + gw * 4;
#pragma unroll
        for (int q = 0; q < 4; q++) {
            int4 v;
            v.x = nb2 + (q * 4 + 0) * 2 + 1 - (int)((fmask >> (q * 4 + 0)) & 1u);
            v.y = nb2 + (q * 4 + 1) * 2 + 1 - (int)((fmask >> (q * 4 + 1)) & 1u);
            v.z = nb2 + (q * 4 + 2) * 2 + 1 - (int)((fmask >> (q * 4 + 2)) & 1u);
            v.w = nb2 + (q * 4 + 3) * 2 + 1 - (int)((fmask >> (q * 4 + 3)) & 1u);
            dst[q] = v;
        }
    }

#pragma unroll
    for (int off = 16; off > 0; off >>= 1)
        local += __shfl_down_sync(0xffffffffu, local, off);
    int lane = t & 31;
    int warp = t >> 5;
    if (lane == 0) ssum[warp] = local;
    __syncthreads();
    if (warp == 0) {
        float v = (lane < 8) ? ssum[lane] : 0.0f;
#pragma unroll
        for (int off = 4; off > 0; off >>= 1)
            v += __shfl_down_sync(0xffffffffu, v, off);
        if (lane == 0) atomicAdd(&g_sum, (double)(0.5f * v));
    }
}

// ---------------------------------------------------------------------------
// union-find with flag-carrying values
// ---------------------------------------------------------------------------
__device__ __forceinline__ int find_root(int* par, int l) {  // halving
    int v = par[l];
    int pidx = v >> 1;
    while (pidx != l) {
        int v2 = par[pidx];
        int gp = v2 >> 1;
        if (gp != pidx) par[l] = v2;   // l observed non-root; store valid ancestor ptr
        l = pidx;
        pidx = gp;
    }
    return l;
}

__device__ __forceinline__ void pushflag(int* par, int r) {
    while (true) {
        int v = par[r];
        int idx = v >> 1;
        if (idx != r) { r = idx; continue; }   // walk toward root
        if (!(v & 1)) return;                  // already flagged
        int old = atomicMin(&par[r], r * 2);
        if ((old >> 1) == r) return;           // flagged it (or it already was)
        r = old >> 1;                          // got linked concurrently; chase
    }
}

__device__ __forceinline__ void unite(int* par, int a, int b) {
    while (true) {
        a = find_root(par, a);
        b = find_root(par, b);
        if (a == b) return;
        if (a < b) { int tmp = a; a = b; b = tmp; }   // a > b: link a -> b
        int old = atomicMin(&par[a], b * 2 + 1);
        if ((old >> 1) == a) {                 // a was root; link installed
            if (!(old & 1)) pushflag(par, b);  // a carried a flag -> push to b
            return;
        }
        a = old >> 1;                          // lost race; retry
    }
}

// post-merge find with FULL path compression; returns root, sets *fl.
__device__ __forceinline__ int find_flag(int* par, int l, bool* fl) {
    int start = l;
    int v = par[l];
    int pidx = v >> 1;
    while (pidx != l) { l = pidx; v = par[l]; pidx = v >> 1; }
    *fl = !(v & 1);
    int cur = start;
    while (cur != l) {
        int nx = par[cur] >> 1;
        if (nx != l) par[cur] = l * 2 + 1;
        cur = nx;
    }
    return l;
}

// ---------------------------------------------------------------------------
// k_merge: 2 threads per (word, tree). Thread h owns vertical overlap-segment
// starts in bit range [16h, 16h+16); h==0 also does the cross-word horiz link.
// ---------------------------------------------------------------------------
__global__ __launch_bounds__(256) void k_merge() {
    int i = blockIdx.x * blockDim.x + threadIdx.x;   // 0 .. 4*NW-1
    int tree = (i >= 2 * NW);
    int r = tree ? i - 2 * NW : i;
    int w = r >> 1, h = r & 1;
    int* par;
    const unsigned int* bm;
    if (tree) { par = g_parT; bm = g_bmT; }
    else      { par = g_parP; bm = g_bmP; }
    unsigned int c = bm[w];
    if (!c) return;
    unsigned int rs = c & ~(c << 1);           // run starts in this word
    int nbase = w * 16;
    unsigned int hm = h ? 0xFFFF0000u : 0x0000FFFFu;
    int row = w >> 5;
    if (row & (HH - 1)) {                      // not first row of image
        unsigned int u = bm[w - 32];
        unsigned int o = c & u;
        if (o) {
            unsigned int s = (o & ~(o << 1)) & hm;   // this half's segment starts
            if (s) {
                unsigned int urs = u & ~(u << 1);
                do {
                    int k = __ffs(s) - 1; s &= s - 1;
                    unsigned int mk = ((1u << k) << 1) - 1u;   // bits 0..k
                    int rc = __popc(rs & mk) - 1;
                    int ru = __popc(urs & mk) - 1;
                    unite(par, nbase + rc, (w - 32) * 16 + ru);
                } while (s);
            }
        }
    }
    if (h == 0 && (w & 31) && (c & 1u)) {      // horizontal cross-word link
        unsigned int pc = bm[w - 1];
        if (pc >> 31) {
            unsigned int prs = pc & ~(pc << 1);
            unite(par, nbase, (w - 1) * 16 + __popc(prs) - 1);
        }
    }
}

// ---------------------------------------------------------------------------
// k_fuse: 2 threads per (word, tree). Thread h owns runs STARTING in its half;
// per flagged run, sums fp16 loss over the run's span only.
// ---------------------------------------------------------------------------
__global__ __launch_bounds__(256) void k_fuse() {
    int i = blockIdx.x * blockDim.x + threadIdx.x;   // 0 .. 4*NW-1
    int tree = (i >= 2 * NW);
    int r = tree ? i - 2 * NW : i;
    int w = r >> 1, h = r & 1;
    int* par;
    unsigned int c;
    if (tree) { par = g_parT; c = g_bmT[w]; }
    else      { par = g_parP; c = g_bmP[w]; }
    float local = 0.0f;
    if (c) {
        unsigned int rs = c & ~(c << 1);
        unsigned int hm = h ? 0xFFFF0000u : 0x0000FFFFu;
        unsigned int myruns = rs & hm;
        if (myruns) {
            const unsigned int* Lw = reinterpret_cast<const unsigned int*>(g_loss) + w * 16;
            do {
                int s = __ffs(myruns) - 1; myruns &= myruns - 1;
                int ridx = __popc(rs & ((1u << s) - 1u));
                bool fl;
                find_flag(par, w * 16 + ridx, &fl);
                if (fl) {
                    // run span: bits s..(first zero after s)-1
                    unsigned int rest = (~c) & ((s == 31) ? 0x80000000u : (0xFFFFFFFFu << s));
                    int e = rest ? (__ffs(rest) - 1) : 32;
                    unsigned int runmask = ((e < 32 ? ((1u << e) - 1u) : 0xFFFFFFFFu)
                                            & (0xFFFFFFFFu << s));
                    int hi = e - 1;
                    for (int h2 = (s >> 1); h2 <= (hi >> 1); h2++) {
                        unsigned int u = Lw[h2];
                        __half2 hh = *reinterpret_cast<__half2*>(&u);
                        float2 f = __half22float2(hh);
                        if (runmask & (1u << (2 * h2)))     local += f.x;
                        if (runmask & (1u << (2 * h2 + 1))) local += f.y;
                    }
                }
            } while (myruns);
            local *= 0.25f;
        }
    }
#pragma unroll
    for (int off = 16; off > 0; off >>= 1)
        local += __shfl_down_sync(0xffffffffu, local, off);
    __shared__ float ssum[8];
    int lane = threadIdx.x & 31;
    int warp = threadIdx.x >> 5;
    if (lane == 0) ssum[warp] = local;
    __syncthreads();
    if (warp == 0) {
        float v = (lane < (blockDim.x >> 5)) ? ssum[lane] : 0.0f;
#pragma unroll
        for (int off = 4; off > 0; off >>= 1)
            v += __shfl_down_sync(0xffffffffu, v, off);
        if (lane == 0 && v != 0.0f)
            atomicAdd(&g_psum[blockIdx.x & 63], (double)v);
    }
}

__global__ void k_out(float* __restrict__ out) {
    double s = g_sum;
#pragma unroll
    for (int i = 0; i < 64; i++) s += g_psum[i];
    out[0] = (float)(s / (double)NTOT);
}

// ---------------------------------------------------------------------------
extern "C" void kernel_launch(void* const* d_in, const int* in_sizes, int n_in,
                              void* d_out, int out_size) {
    const float* preds = (const float*)d_in[0];
    const float* targs = (const float*)d_in[1];
    float* out = (float*)d_out;

    k_zero <<<1, 64>>>();
    k_init <<<NTOT / 1024, 256>>>(preds, targs);
    k_merge<<<4 * NW / 256, 256>>>();
    k_fuse <<<4 * NW / 256, 256>>>();
    k_out  <<<1, 1>>>(out);
}

// round 13
// speedup vs baseline: 1.1443x; 1.1443x over previous
#include <cuda_runtime.h>
#include <cuda_fp16.h>
#include <math.h>

#define BATCH 16
#define HH 1024
#define WW 1024
#define NPIX (HH*WW)
#define NTOT (BATCH*NPIX)
#define NW   (NTOT/32)          // 524288 bitmap words
#define NODE (NW*16)            // <=16 runs per 32-bit word

// Value encoding in par[]: v = idx*2 + (flag ? 0 : 1) for root slots;
// non-root slots hold parent pointer idx in bits [1..], bit0 = don't-care (1).
// atomicMin: idx dominates; flagged < unflagged at equal idx, so flags never
// clear and links only decrease idx.

// Scratch (__device__ globals; no allocation)
__device__ int g_parP[NODE];
__device__ int g_parT[NODE];
__device__ unsigned int g_bmP[NW];
__device__ unsigned int g_bmT[NW];
__device__ __half2 g_loss[NTOT/2];  // fp16 per-pixel BCE loss (32 MB)
__device__ double g_sum;
__device__ double g_psum[64];

// ---------------------------------------------------------------------------
__global__ void k_zero() {
    int t = threadIdx.x;
    if (t == 0) g_sum = 0.0;
    if (t < 64) g_psum[t] = 0.0;
}

// ---------------------------------------------------------------------------
// k_init: bitmaps + fp16 loss + 0.5*sum(loss) + parent init with per-run
// mistake flags baked into the initial values. One block = one 1024-px row.
// ---------------------------------------------------------------------------
__global__ __launch_bounds__(256) void k_init(const float* __restrict__ preds,
                                              const float* __restrict__ targs) {
    __shared__ unsigned char snP[256], snT[256];
    __shared__ unsigned short sfm[2][32];   // per-word run-flag masks (P, T)
    __shared__ float ssum[8];
    int t = threadIdx.x;
    int i4 = blockIdx.x * 256 + t;
    float4 p  = reinterpret_cast<const float4*>(preds)[i4];
    float4 tg = reinterpret_cast<const float4*>(targs)[i4];
    unsigned int nP = (unsigned int)(p.x  > 0.5f) | ((unsigned int)(p.y  > 0.5f) << 1)
                    | ((unsigned int)(p.z  > 0.5f) << 2) | ((unsigned int)(p.w  > 0.5f) << 3);
    unsigned int nT = (unsigned int)(tg.x > 0.0f) | ((unsigned int)(tg.y > 0.0f) << 1)
                    | ((unsigned int)(tg.z > 0.0f) << 2) | ((unsigned int)(tg.w > 0.0f) << 3);
    snP[t] = (unsigned char)nP;
    snT[t] = (unsigned char)nT;

    float pv[4] = {p.x, p.y, p.z, p.w};
    float tv[4] = {tg.x, tg.y, tg.z, tg.w};
    float lv[4];
    float local = 0.0f;
#pragma unroll
    for (int j = 0; j < 4; j++) {
        float pp = pv[j];
        float e = __expf(-fabsf(pp));
        float l = fmaxf(pp, 0.0f) - pp * tv[j] + __logf(1.0f + e);
        lv[j] = l;
        local += l;
    }
    __half2 h0 = __floats2half2_rn(lv[0], lv[1]);
    __half2 h1 = __floats2half2_rn(lv[2], lv[3]);
    uint2 packed;
    packed.x = *reinterpret_cast<unsigned int*>(&h0);
    packed.y = *reinterpret_cast<unsigned int*>(&h1);
    reinterpret_cast<uint2*>(g_loss)[i4] = packed;
    __syncthreads();

    if (t < 64) {
        int w = t >> 1;
        int half = t & 1;
        const unsigned char* sn = half ? snT : snP;
        const unsigned char* so = half ? snP : snT;
        unsigned int word = 0, other = 0;
#pragma unroll
        for (int j = 0; j < 8; j++) {
            word  |= ((unsigned int)sn[w * 8 + j]) << (4 * j);
            other |= ((unsigned int)so[w * 8 + j]) << (4 * j);
        }
        int gw = blockIdx.x * 32 + w;
        if (half) g_bmT[gw] = word;
        else      g_bmP[gw] = word;

        // per-run mistake flags
        unsigned int mistake = word & ~other;
        unsigned int rr = word & ~(word << 1);
        unsigned int fmask = 0;
        int ridx = 0;
        while (rr) {
            int s = __ffs(rr) - 1; rr &= rr - 1;
            int e = rr ? (__ffs(rr) - 1) : 32;
            unsigned int seg = (e < 32 ? ((1u << e) - 1u) : ~0u) & (~0u << s);
            if (mistake & seg) fmask |= (1u << ridx);
            ridx++;
        }
        sfm[half][w] = (unsigned short)fmask;
    }
    __syncthreads();

    // distributed parent init: one int4 per thread (256 threads = 2 trees x
    // 32 words x 4 quads), coalesced
    {
        int tree = t >> 7;
        int rem = t & 127;
        int wir = rem >> 2;     // word in row
        int q = rem & 3;        // quad within word's 16 slots
        unsigned int fmask = (unsigned int)sfm[tree][wir];
        int gw = blockIdx.x * 32 + wir;
        int nb2 = gw * 32;      // (gw*16)*2
        int4 v;
        v.x = nb2 + (q * 4 + 0) * 2 + 1 - (int)((fmask >> (q * 4 + 0)) & 1u);
        v.y = nb2 + (q * 4 + 1) * 2 + 1 - (int)((fmask >> (q * 4 + 1)) & 1u);
        v.z = nb2 + (q * 4 + 2) * 2 + 1 - (int)((fmask >> (q * 4 + 2)) & 1u);
        v.w = nb2 + (q * 4 + 3) * 2 + 1 - (int)((fmask >> (q * 4 + 3)) & 1u);
        int4* dst = (tree ? reinterpret_cast<int4*>(g_parT)
                          : reinterpret_cast<int4*>(g_parP)) + gw * 4 + q;
        *dst = v;
    }

#pragma unroll
    for (int off = 16; off > 0; off >>= 1)
        local += __shfl_down_sync(0xffffffffu, local, off);
    int lane = t & 31;
    int warp = t >> 5;
    if (lane == 0) ssum[warp] = local;
    __syncthreads();
    if (warp == 0) {
        float v = (lane < 8) ? ssum[lane] : 0.0f;
#pragma unroll
        for (int off = 4; off > 0; off >>= 1)
            v += __shfl_down_sync(0xffffffffu, v, off);
        if (lane == 0) atomicAdd(&g_sum, (double)(0.5f * v));
    }
}

// ---------------------------------------------------------------------------
// union-find with flag-carrying values
// ---------------------------------------------------------------------------
__device__ __forceinline__ int find_root(int* par, int l) {  // halving
    int v = par[l];
    int pidx = v >> 1;
    while (pidx != l) {
        int v2 = par[pidx];
        int gp = v2 >> 1;
        if (gp != pidx) par[l] = v2;   // l observed non-root; store valid ancestor ptr
        l = pidx;
        pidx = gp;
    }
    return l;
}

__device__ __forceinline__ void pushflag(int* par, int r) {
    while (true) {
        int v = par[r];
        int idx = v >> 1;
        if (idx != r) { r = idx; continue; }   // walk toward root
        if (!(v & 1)) return;                  // already flagged
        int old = atomicMin(&par[r], r * 2);
        if ((old >> 1) == r) return;           // flagged it (or it already was)
        r = old >> 1;                          // got linked concurrently; chase
    }
}

__device__ __forceinline__ void unite(int* par, int a, int b) {
    while (true) {
        a = find_root(par, a);
        b = find_root(par, b);
        if (a == b) return;
        if (a < b) { int tmp = a; a = b; b = tmp; }   // a > b: link a -> b
        int old = atomicMin(&par[a], b * 2 + 1);
        if ((old >> 1) == a) {                 // a was root; link installed
            if (!(old & 1)) pushflag(par, b);  // a carried a flag -> push to b
            return;
        }
        a = old >> 1;                          // lost race; retry
    }
}

// post-merge find with FULL path compression; returns root, sets *fl.
__device__ __forceinline__ int find_flag(int* par, int l, bool* fl) {
    int start = l;
    int v = par[l];
    int pidx = v >> 1;
    while (pidx != l) { l = pidx; v = par[l]; pidx = v >> 1; }
    *fl = !(v & 1);
    int cur = start;
    while (cur != l) {
        int nx = par[cur] >> 1;
        if (nx != l) par[cur] = l * 2 + 1;
        cur = nx;
    }
    return l;
}

// ---------------------------------------------------------------------------
// k_merge: per (word, tree): cross-word horiz link + vertical overlap starts
// ---------------------------------------------------------------------------
__global__ void k_merge() {
    int i = blockIdx.x * blockDim.x + threadIdx.x;
    if (i >= 2 * NW) return;
    int w = (i >= NW) ? (i - NW) : i;
    int* par;
    const unsigned int* bm;
    if (i >= NW) { par = g_parT; bm = g_bmT; }
    else         { par = g_parP; bm = g_bmP; }
    unsigned int c = bm[w];
    if (!c) return;
    unsigned int rs = c & ~(c << 1);           // run starts in this word
    int nbase = w * 16;
    if ((w & 31) && (c & 1u)) {
        unsigned int pc = bm[w - 1];
        if (pc >> 31) {
            unsigned int prs = pc & ~(pc << 1);
            unite(par, nbase, (w - 1) * 16 + __popc(prs) - 1);
        }
    }
    int row = w >> 5;
    if (row & (HH - 1)) {                      // not first row of image
        unsigned int u = bm[w - 32];
        unsigned int o = c & u;
        if (o) {
            unsigned int urs = u & ~(u << 1);
            unsigned int s = o & ~(o << 1);    // overlap-segment starts
            while (s) {
                int k = __ffs(s) - 1; s &= s - 1;
                unsigned int mk = ((1u << k) << 1) - 1u;   // bits 0..k
                int rc = __popc(rs & mk) - 1;
                int ru = __popc(urs & mk) - 1;
                unite(par, nbase + rc, (w - 32) * 16 + ru);
            }
        }
    }
}

// ---------------------------------------------------------------------------
// k_fuse: per (word, tree): find per run -> flag bits -> 0.25*sum(flagged loss)
// ---------------------------------------------------------------------------
__global__ __launch_bounds__(256) void k_fuse() {
    int i = blockIdx.x * blockDim.x + threadIdx.x;
    int w = (i >= NW) ? (i - NW) : i;
    int* par;
    unsigned int c;
    if (i >= NW) { par = g_parT; c = g_bmT[w]; }
    else         { par = g_parP; c = g_bmP[w]; }
    float local = 0.0f;
    if (c) {
        unsigned int res = 0;
        unsigned int runs = c & ~(c << 1);
        int ridx = 0;
        while (runs) {
            int s = __ffs(runs) - 1; runs &= runs - 1;
            int e = runs ? (__ffs(runs) - 1) : 32;
            bool fl;
            find_flag(par, w * 16 + ridx, &fl);
            if (fl) res |= (e < 32 ? ((1u << e) - 1u) : ~0u) & (~0u << s);
            ridx++;
        }
        res &= c;
        if (res) {
            const uint4* L = reinterpret_cast<const uint4*>(g_loss) + w * 4;
            float sum = 0.0f;
#pragma unroll
            for (int q = 0; q < 4; q++) {
                uint4 v = L[q];
                unsigned int r8 = res >> (q * 8);
                unsigned int uu[4] = {v.x, v.y, v.z, v.w};
#pragma unroll
                for (int h = 0; h < 4; h++) {
                    unsigned int u = uu[h];
                    __half2 hh = *reinterpret_cast<__half2*>(&u);
                    float2 f = __half22float2(hh);
                    if (r8 & 1u) sum += f.x;
                    if (r8 & 2u) sum += f.y;
                    r8 >>= 2;
                }
            }
            local = 0.25f * sum;
        }
    }
#pragma unroll
    for (int off = 16; off > 0; off >>= 1)
        local += __shfl_down_sync(0xffffffffu, local, off);
    __shared__ float ssum[8];
    int lane = threadIdx.x & 31;
    int warp = threadIdx.x >> 5;
    if (lane == 0) ssum[warp] = local;
    __syncthreads();
    if (warp == 0) {
        float v = (lane < (blockDim.x >> 5)) ? ssum[lane] : 0.0f;
#pragma unroll
        for (int off = 4; off > 0; off >>= 1)
            v += __shfl_down_sync(0xffffffffu, v, off);
        if (lane == 0 && v != 0.0f)
            atomicAdd(&g_psum[blockIdx.x & 63], (double)v);
    }
}

__global__ void k_out(float* __restrict__ out) {
    double s = g_sum;
#pragma unroll
    for (int i = 0; i < 64; i++) s += g_psum[i];
    out[0] = (float)(s / (double)NTOT);
}

// ---------------------------------------------------------------------------
extern "C" void kernel_launch(void* const* d_in, const int* in_sizes, int n_in,
                              void* d_out, int out_size) {
    const float* preds = (const float*)d_in[0];
    const float* targs = (const float*)d_in[1];
    float* out = (float*)d_out;

    k_zero <<<1, 64>>>();
    k_init <<<NTOT / 1024, 256>>>(preds, targs);
    k_merge<<<2 * NW / 256, 256>>>();
    k_fuse <<<2 * NW / 256, 256>>>();
    k_out  <<<1, 1>>>(out);
}

// round 16
// speedup vs baseline: 1.1823x; 1.0332x over previous
#include <cuda_runtime.h>
#include <cuda_fp16.h>
#include <math.h>

#define BATCH 16
#define HH 1024
#define WW 1024
#define NPIX (HH*WW)
#define NTOT (BATCH*NPIX)
#define NW   (NTOT/32)          // 524288 bitmap words
#define NODE (NW*16)            // <=16 runs per 32-bit word

// Value encoding in par[]: v = idx*2 + (flag ? 0 : 1) for root slots;
// non-root slots hold parent pointer idx in bits [1..], bit0 = don't-care (1).
// atomicMin: idx dominates; flagged < unflagged at equal idx, so flags never
// clear and links only decrease idx.

// Scratch (__device__ globals; no allocation)
__device__ int g_parP[NODE];
__device__ int g_parT[NODE];
__device__ unsigned int g_bmP[NW];
__device__ unsigned int g_bmT[NW];
__device__ __half2 g_loss[NTOT/2];  // fp16 per-pixel BCE loss (32 MB)
__device__ double g_sum;
__device__ double g_psum[64];

// ---------------------------------------------------------------------------
__global__ void k_zero() {
    int t = threadIdx.x;
    if (t == 0) g_sum = 0.0;
    if (t < 64) g_psum[t] = 0.0;
}

// ---------------------------------------------------------------------------
// k_init: bitmaps + fp16 loss + 0.5*sum(loss) + parent init with per-run
// mistake flags baked into the initial values. One block = one 1024-px row.
// ---------------------------------------------------------------------------
__global__ __launch_bounds__(256) void k_init(const float* __restrict__ preds,
                                              const float* __restrict__ targs) {
    __shared__ unsigned char snP[256], snT[256];
    __shared__ unsigned short sfm[2][32];   // per-word run-flag masks (P, T)
    __shared__ float ssum[8];
    int t = threadIdx.x;
    int i4 = blockIdx.x * 256 + t;
    float4 p  = reinterpret_cast<const float4*>(preds)[i4];
    float4 tg = reinterpret_cast<const float4*>(targs)[i4];
    unsigned int nP = (unsigned int)(p.x  > 0.5f) | ((unsigned int)(p.y  > 0.5f) << 1)
                    | ((unsigned int)(p.z  > 0.5f) << 2) | ((unsigned int)(p.w  > 0.5f) << 3);
    unsigned int nT = (unsigned int)(tg.x > 0.0f) | ((unsigned int)(tg.y > 0.0f) << 1)
                    | ((unsigned int)(tg.z > 0.0f) << 2) | ((unsigned int)(tg.w > 0.0f) << 3);
    snP[t] = (unsigned char)nP;
    snT[t] = (unsigned char)nT;

    float pv[4] = {p.x, p.y, p.z, p.w};
    float tv[4] = {tg.x, tg.y, tg.z, tg.w};
    float lv[4];
    float local = 0.0f;
#pragma unroll
    for (int j = 0; j < 4; j++) {
        float pp = pv[j];
        float e = __expf(-fabsf(pp));
        float l = fmaxf(pp, 0.0f) - pp * tv[j] + __logf(1.0f + e);
        lv[j] = l;
        local += l;
    }
    __half2 h0 = __floats2half2_rn(lv[0], lv[1]);
    __half2 h1 = __floats2half2_rn(lv[2], lv[3]);
    uint2 packed;
    packed.x = *reinterpret_cast<unsigned int*>(&h0);
    packed.y = *reinterpret_cast<unsigned int*>(&h1);
    reinterpret_cast<uint2*>(g_loss)[i4] = packed;
    __syncthreads();

    if (t < 64) {
        int w = t >> 1;
        int half = t & 1;
        const unsigned char* sn = half ? snT : snP;
        const unsigned char* so = half ? snP : snT;
        unsigned int word = 0, other = 0;
#pragma unroll
        for (int j = 0; j < 8; j++) {
            word  |= ((unsigned int)sn[w * 8 + j]) << (4 * j);
            other |= ((unsigned int)so[w * 8 + j]) << (4 * j);
        }
        int gw = blockIdx.x * 32 + w;
        if (half) g_bmT[gw] = word;
        else      g_bmP[gw] = word;

        // per-run mistake flags
        unsigned int mistake = word & ~other;
        unsigned int rr = word & ~(word << 1);
        unsigned int fmask = 0;
        int ridx = 0;
        while (rr) {
            int s = __ffs(rr) - 1; rr &= rr - 1;
            int e = rr ? (__ffs(rr) - 1) : 32;
            unsigned int seg = (e < 32 ? ((1u << e) - 1u) : ~0u) & (~0u << s);
            if (mistake & seg) fmask |= (1u << ridx);
            ridx++;
        }
        sfm[half][w] = (unsigned short)fmask;
    }
    __syncthreads();

    // distributed parent init: one int4 per thread (256 threads = 2 trees x
    // 32 words x 4 quads), coalesced
    {
        int tree = t >> 7;
        int rem = t & 127;
        int wir = rem >> 2;     // word in row
        int q = rem & 3;        // quad within word's 16 slots
        unsigned int fmask = (unsigned int)sfm[tree][wir];
        int gw = blockIdx.x * 32 + wir;
        int nb2 = gw * 32;      // (gw*16)*2
        int4 v;
        v.x = nb2 + (q * 4 + 0) * 2 + 1 - (int)((fmask >> (q * 4 + 0)) & 1u);
        v.y = nb2 + (q * 4 + 1) * 2 + 1 - (int)((fmask >> (q * 4 + 1)) & 1u);
        v.z = nb2 + (q * 4 + 2) * 2 + 1 - (int)((fmask >> (q * 4 + 2)) & 1u);
        v.w = nb2 + (q * 4 + 3) * 2 + 1 - (int)((fmask >> (q * 4 + 3)) & 1u);
        int4* dst = (tree ? reinterpret_cast<int4*>(g_parT)
                          : reinterpret_cast<int4*>(g_parP)) + gw * 4 + q;
        *dst = v;
    }

#pragma unroll
    for (int off = 16; off > 0; off >>= 1)
        local += __shfl_down_sync(0xffffffffu, local, off);
    int lane = t & 31;
    int warp = t >> 5;
    if (lane == 0) ssum[warp] = local;
    __syncthreads();
    if (warp == 0) {
        float v = (lane < 8) ? ssum[lane] : 0.0f;
#pragma unroll
        for (int off = 4; off > 0; off >>= 1)
            v += __shfl_down_sync(0xffffffffu, v, off);
        if (lane == 0) atomicAdd(&g_sum, (double)(0.5f * v));
    }
}

// ---------------------------------------------------------------------------
// union-find with flag-carrying values
// ---------------------------------------------------------------------------
__device__ __forceinline__ int find_root(int* par, int l) {  // halving
    int v = par[l];
    int pidx = v >> 1;
    while (pidx != l) {
        int v2 = par[pidx];
        int gp = v2 >> 1;
        if (gp != pidx) par[l] = v2;   // l observed non-root; store valid ancestor ptr
        l = pidx;
        pidx = gp;
    }
    return l;
}

__device__ __forceinline__ void pushflag(int* par, int r) {
    while (true) {
        int v = par[r];
        int idx = v >> 1;
        if (idx != r) { r = idx; continue; }   // walk toward root
        if (!(v & 1)) return;                  // already flagged
        int old = atomicMin(&par[r], r * 2);
        if ((old >> 1) == r) return;           // flagged it (or it already was)
        r = old >> 1;                          // got linked concurrently; chase
    }
}

__device__ __forceinline__ void unite(int* par, int a, int b) {
    while (true) {
        a = find_root(par, a);
        b = find_root(par, b);
        if (a == b) return;
        if (a < b) { int tmp = a; a = b; b = tmp; }   // a > b: link a -> b
        int old = atomicMin(&par[a], b * 2 + 1);
        if ((old >> 1) == a) {                 // a was root; link installed
            if (!(old & 1)) pushflag(par, b);  // a carried a flag -> push to b
            return;
        }
        a = old >> 1;                          // lost race; retry
    }
}

// single-pass halving find that returns the root's flag (no second pass;
// fuse is the last reader of par[], full compression is wasted bandwidth)
__device__ __forceinline__ bool flag_of(int* par, int l) {
    int v = par[l];
    int pidx = v >> 1;
    while (pidx != l) {
        int v2 = par[pidx];
        int gp = v2 >> 1;
        if (gp != pidx) par[l] = v2;   // halving store (valid ancestor)
        l = pidx;
        v = v2;
        pidx = gp;
    }
    return !(v & 1);
}

// ---------------------------------------------------------------------------
// k_merge: per (word, tree): cross-word horiz link + vertical overlap starts
// ---------------------------------------------------------------------------
__global__ void k_merge() {
    int i = blockIdx.x * blockDim.x + threadIdx.x;
    if (i >= 2 * NW) return;
    int w = (i >= NW) ? (i - NW) : i;
    int* par;
    const unsigned int* bm;
    if (i >= NW) { par = g_parT; bm = g_bmT; }
    else         { par = g_parP; bm = g_bmP; }
    unsigned int c = bm[w];
    if (!c) return;
    unsigned int rs = c & ~(c << 1);           // run starts in this word
    int nbase = w * 16;
    if ((w & 31) && (c & 1u)) {
        unsigned int pc = bm[w - 1];
        if (pc >> 31) {
            unsigned int prs = pc & ~(pc << 1);
            unite(par, nbase, (w - 1) * 16 + __popc(prs) - 1);
        }
    }
    int row = w >> 5;
    if (row & (HH - 1)) {                      // not first row of image
        unsigned int u = bm[w - 32];
        unsigned int o = c & u;
        if (o) {
            unsigned int urs = u & ~(u << 1);
            unsigned int s = o & ~(o << 1);    // overlap-segment starts
            while (s) {
                int k = __ffs(s) - 1; s &= s - 1;
                unsigned int mk = ((1u << k) << 1) - 1u;   // bits 0..k
                int rc = __popc(rs & mk) - 1;
                int ru = __popc(urs & mk) - 1;
                unite(par, nbase + rc, (w - 32) * 16 + ru);
            }
        }
    }
}

// ---------------------------------------------------------------------------
// k_fuse: per (word, tree): flag per run -> flag bits -> 0.25*sum(flagged loss)
// ---------------------------------------------------------------------------
__global__ __launch_bounds__(256) void k_fuse() {
    int i = blockIdx.x * blockDim.x + threadIdx.x;
    int w = (i >= NW) ? (i - NW) : i;
    int* par;
    unsigned int c;
    if (i >= NW) { par = g_parT; c = g_bmT[w]; }
    else         { par = g_parP; c = g_bmP[w]; }
    float local = 0.0f;
    if (c) {
        unsigned int res = 0;
        unsigned int runs = c & ~(c << 1);
        int ridx = 0;
        while (runs) {
            int s = __ffs(runs) - 1; runs &= runs - 1;
            int e = runs ? (__ffs(runs) - 1) : 32;
            if (flag_of(par, w * 16 + ridx))
                res |= (e < 32 ? ((1u << e) - 1u) : ~0u) & (~0u << s);
            ridx++;
        }
        res &= c;
        if (res) {
            const uint4* L = reinterpret_cast<const uint4*>(g_loss) + w * 4;
            float sum = 0.0f;
#pragma unroll
            for (int q = 0; q < 4; q++) {
                uint4 v = L[q];
                unsigned int r8 = res >> (q * 8);
                unsigned int uu[4] = {v.x, v.y, v.z, v.w};
#pragma unroll
                for (int h = 0; h < 4; h++) {
                    unsigned int u = uu[h];
                    __half2 hh = *reinterpret_cast<__half2*>(&u);
                    float2 f = __half22float2(hh);
                    if (r8 & 1u) sum += f.x;
                    if (r8 & 2u) sum += f.y;
                    r8 >>= 2;
                }
            }
            local = 0.25f * sum;
        }
    }
#pragma unroll
    for (int off = 16; off > 0; off >>= 1)
        local += __shfl_down_sync(0xffffffffu, local, off);
    __shared__ float ssum[8];
    int lane = threadIdx.x & 31;
    int warp = threadIdx.x >> 5;
    if (lane == 0) ssum[warp] = local;
    __syncthreads();
    if (warp == 0) {
        float v = (lane < (blockDim.x >> 5)) ? ssum[lane] : 0.0f;
#pragma unroll
        for (int off = 4; off > 0; off >>= 1)
            v += __shfl_down_sync(0xffffffffu, v, off);
        if (lane == 0 && v != 0.0f)
            atomicAdd(&g_psum[blockIdx.x & 63], (double)v);
    }
}

__global__ void k_out(float* __restrict__ out) {
    double s = g_sum;
#pragma unroll
    for (int i = 0; i < 64; i++) s += g_psum[i];
    out[0] = (float)(s / (double)NTOT);
}

// ---------------------------------------------------------------------------
extern "C" void kernel_launch(void* const* d_in, const int* in_sizes, int n_in,
                              void* d_out, int out_size) {
    const float* preds = (const float*)d_in[0];
    const float* targs = (const float*)d_in[1];
    float* out = (float*)d_out;

    k_zero <<<1, 64>>>();
    k_init <<<NTOT / 1024, 256>>>(preds, targs);
    k_merge<<<2 * NW / 256, 256>>>();
    k_fuse <<<2 * NW / 256, 256>>>();
    k_out  <<<1, 1>>>(out);
}